// round 14
// baseline (speedup 1.0000x reference)
#include <cuda_runtime.h>
#include <cuda_fp16.h>
#include <cstdint>
#include <cstddef>

// ---------------------------------------------------------------------------
#define BB 8
#define CC 256
#define SS 1024
#define NH 8
#define DK 256
#define HD 2048
#define QKVN 6144

#define BM 128
#define BN 128
#define BKF 32                     // K elements per block
#define PAD 40                     // fp16 per smem row (80B; ldsm conflict-free)
#define TILEB (128 * PAD * 2)      // 10240 B per tile
#define STAGEB (2 * TILEB)         // A, B
#define NSTAGE 5
#define SMEM_DYN (NSTAGE * STAGEB) // 102400 B (2 CTAs/SM)
#define SCP 132                    // fp16 pad for V-transpose staging

// fused attention smem layout (bytes)
#define QSTR 528                   // 264 fp16 row stride (odd x16B)
#define VSTR 272                   // 136 fp16 row stride
#define OFF_Q 0
#define OFF_K 33792                // 64*528
#define OFF_V 101376               // OFF_K + 128*528
#define OFF_P 171008               // OFF_V + 256*272
#define OFF_RS 188416              // OFF_P + 64*272
#define SMEM_FA 188672

typedef __half fp16;

// ---------------------------------------------------------------------------
// Device scratch (allocation-free)
// ---------------------------------------------------------------------------
__device__ __align__(128) fp16 g_xt[BB * SS * CC];        // [b*S+s][c]
__device__ __align__(128) fp16 g_WpT[QKVN * CC];          // [n][k]
__device__ __align__(128) fp16 g_WoT[CC * HD];            // [n][k]
__device__ __align__(128) fp16 g_q[BB * NH * SS * DK];    // [bh][s][d]
__device__ __align__(128) fp16 g_k[BB * NH * SS * DK];    // [bh][s][d]
__device__ __align__(128) fp16 g_v[BB * NH * DK * SS];    // [bh][d][s] TRANSPOSED
__device__ __align__(128) fp16 g_ao[BB * SS * HD];        // [b*S+s][h*DK+d]

// ---------------------------------------------------------------------------
// PTX helpers
// ---------------------------------------------------------------------------
__device__ __forceinline__ uint32_t smem_u32(const void* p) {
    uint32_t a;
    asm("{ .reg .u64 t; cvta.to.shared.u64 t, %1; cvt.u32.u64 %0, t; }"
        : "=r"(a) : "l"(p));
    return a;
}
__device__ __forceinline__ void cpa16(uint32_t dst, const void* src) {
    asm volatile("cp.async.cg.shared.global [%0], [%1], 16;"
                 :: "r"(dst), "l"(src) : "memory");
}
__device__ __forceinline__ void cpa_commit() {
    asm volatile("cp.async.commit_group;" ::: "memory");
}
template <int N> __device__ __forceinline__ void cpa_wait() {
    asm volatile("cp.async.wait_group %0;" :: "n"(N) : "memory");
}
__device__ __forceinline__ void ldsm4(uint32_t* r, uint32_t addr) {
    asm volatile("ldmatrix.sync.aligned.m8n8.x4.shared.b16 {%0,%1,%2,%3}, [%4];"
                 : "=r"(r[0]), "=r"(r[1]), "=r"(r[2]), "=r"(r[3]) : "r"(addr));
}
__device__ __forceinline__ void mma16816(float* d, const uint32_t* a,
                                         uint32_t b0, uint32_t b1) {
    asm volatile(
        "mma.sync.aligned.m16n8k16.row.col.f32.f16.f16.f32 "
        "{%0,%1,%2,%3}, {%4,%5,%6,%7}, {%8,%9}, {%0,%1,%2,%3};"
        : "+f"(d[0]), "+f"(d[1]), "+f"(d[2]), "+f"(d[3])
        : "r"(a[0]), "r"(a[1]), "r"(a[2]), "r"(a[3]), "r"(b0), "r"(b1));
}

// ---------------------------------------------------------------------------
// fp32 [Z][R][C] -> transposed fp16 [Z][C][R]
// ---------------------------------------------------------------------------
__global__ __launch_bounds__(256) void convT(const float* __restrict__ in,
                                             fp16* __restrict__ o, int R, int C) {
    __shared__ float t[32][33];
    int z = blockIdx.z;
    const float* I = in + (size_t)z * R * C;
    size_t ob = (size_t)z * R * C;
    int c0 = blockIdx.x * 32, r0 = blockIdx.y * 32;
    int x = threadIdx.x, y = threadIdx.y;
#pragma unroll
    for (int i = 0; i < 32; i += 8)
        t[y + i][x] = I[(size_t)(r0 + y + i) * C + c0 + x];
    __syncthreads();
#pragma unroll
    for (int i = 0; i < 32; i += 8)
        o[ob + (size_t)(c0 + y + i) * R + r0 + x] = __float2half(t[x][y + i]);
}

// ---------------------------------------------------------------------------
// fp16 GEMM (R11 mainloop): 5-stage cp.async, split A/B issue, 1 sync/iter.
// MODE 0: QKV -> bias; Q/K scattered; V written TRANSPOSED via smem staging
// MODE 3: proj -> bias + residual + transposed fp32 store
// ---------------------------------------------------------------------------
template <int MODE>
__global__ __launch_bounds__(256, 2) void gemm_fp16(
    const fp16* __restrict__ A, const fp16* __restrict__ B,
    float* __restrict__ C, int K, int ldA, int ldB,
    const float* __restrict__ bias, const float* __restrict__ resid) {
    extern __shared__ __align__(16) char dynsm[];
    const uint32_t sbase = smem_u32(dynsm);

    const int tid = threadIdx.x;
    const int wid = tid >> 5;
    const int lane = tid & 31;
    const int wr = wid >> 1;
    const int wc = wid & 1;

    const int m0 = blockIdx.y * BM;
    const int n0 = blockIdx.x * BN;
    const fp16* tA = A + (size_t)m0 * ldA;
    const fp16* tB = B + (size_t)n0 * ldB;
    const int NKB = K / BKF;

    const int crow = tid >> 1;
    const int ccol = (tid & 1) * 16;

    auto issueA = [&](int kb, int stg) {
        uint32_t sb = sbase + stg * STAGEB + (crow * PAD + ccol) * 2;
        const fp16* ga = tA + (size_t)crow * ldA + kb * BKF + ccol;
        cpa16(sb, ga);
        cpa16(sb + 16, ga + 8);
    };
    auto issueB = [&](int kb, int stg) {
        uint32_t sb = sbase + stg * STAGEB + TILEB + (crow * PAD + ccol) * 2;
        const fp16* gb = tB + (size_t)crow * ldB + kb * BKF + ccol;
        cpa16(sb, gb);
        cpa16(sb + 16, gb + 8);
    };

    const int lr = lane & 15, lhf = lane >> 4;
    uint32_t aoff[2], boff[4];
#pragma unroll
    for (int im = 0; im < 2; ++im)
        aoff[im] = ((wr * 32 + im * 16 + lr) * PAD + lhf * 8) * 2;
#pragma unroll
    for (int jn = 0; jn < 4; ++jn)
        boff[jn] = ((wc * 64 + jn * 16 + lr) * PAD + lhf * 8) * 2;

    float acc[2][8][4] = {};

#pragma unroll
    for (int s = 0; s < 4; ++s) {
        issueA(s, s); issueB(s, s); cpa_commit();
    }

    for (int kb = 0; kb < NKB; ++kb) {
        if (kb + 4 <= NKB) cpa_wait<3>();
        else if (kb + 3 == NKB) cpa_wait<2>();
        else if (kb + 2 == NKB) cpa_wait<1>();
        else cpa_wait<0>();
        __syncthreads();

        const bool pf = (kb + 4 < NKB);
        const int pstg = (kb + 4) % NSTAGE;
        if (pf) issueA(kb + 4, pstg);

        const int stg = kb % NSTAGE;
        const uint32_t sA = sbase + stg * STAGEB;
        const uint32_t sB = sA + TILEB;

        uint32_t af[2][2][4], bf[2][4][4];
#pragma unroll
        for (int ks = 0; ks < 2; ++ks) {
            const uint32_t kso = ks * 32;
            ldsm4(af[ks][0], sA + aoff[0] + kso);
            ldsm4(af[ks][1], sA + aoff[1] + kso);
#pragma unroll
            for (int jn = 0; jn < 4; ++jn) ldsm4(bf[ks][jn], sB + boff[jn] + kso);
        }

        if (pf) issueB(kb + 4, pstg);

#pragma unroll
        for (int ks = 0; ks < 2; ++ks)
#pragma unroll
            for (int im = 0; im < 2; ++im)
#pragma unroll
                for (int jn = 0; jn < 4; ++jn) {
                    mma16816(acc[im][jn * 2], af[ks][im], bf[ks][jn][0], bf[ks][jn][2]);
                    mma16816(acc[im][jn * 2 + 1], af[ks][im], bf[ks][jn][1], bf[ks][jn][3]);
                }
        if (pf) cpa_commit();
    }
    __syncthreads();

    const int r0l = lane >> 2;
    const int c0l = (lane & 3) * 2;

    if (MODE == 0) {
        const int hB = n0 / 768;
        const int loc0 = n0 % 768;
        const int seg = loc0 >> 8;
        const int d0 = loc0 & 255;
        if (seg < 2) {
            fp16* dst = (seg == 0) ? g_q : g_k;
#pragma unroll
            for (int im = 0; im < 2; ++im)
#pragma unroll
                for (int jn = 0; jn < 8; ++jn)
#pragma unroll
                    for (int p = 0; p < 2; ++p) {
                        int m = m0 + wr * 32 + im * 16 + r0l + p * 8;
                        int nb = wc * 64 + jn * 8 + c0l;
                        int b = m >> 10, s2 = m & 1023;
                        size_t row = ((size_t)(b * NH + hB) * SS + s2) * DK + d0 + nb;
                        __half2 h;
                        h.x = __float2half(acc[im][jn][p * 2] + bias[n0 + nb]);
                        h.y = __float2half(acc[im][jn][p * 2 + 1] + bias[n0 + nb + 1]);
                        *(__half2*)(dst + row) = h;
                    }
        } else {
            fp16* sc = (fp16*)dynsm;  // 128 x SCP fp16
#pragma unroll
            for (int im = 0; im < 2; ++im)
#pragma unroll
                for (int jn = 0; jn < 8; ++jn)
#pragma unroll
                    for (int p = 0; p < 2; ++p) {
                        int ml = wr * 32 + im * 16 + r0l + p * 8;
                        int nb = wc * 64 + jn * 8 + c0l;
                        sc[ml * SCP + nb] =
                            __float2half(acc[im][jn][p * 2] + bias[n0 + nb]);
                        sc[ml * SCP + nb + 1] =
                            __float2half(acc[im][jn][p * 2 + 1] + bias[n0 + nb + 1]);
                    }
            __syncthreads();
            const int b = m0 >> 10;
            const int s0 = m0 & 1023;
            const int d = tid & 127;
            const int mh = (tid >> 7) * 64;
            fp16* vrow = g_v + ((size_t)(b * NH + hB) * DK + d0 + d) * SS + s0 + mh;
#pragma unroll
            for (int j = 0; j < 64; j += 2) {
                __half2 h;
                h.x = sc[(mh + j) * SCP + d];
                h.y = sc[(mh + j + 1) * SCP + d];
                *(__half2*)(vrow + j) = h;
            }
        }
    } else {  // MODE 3: proj, smem transpose + bias + residual
        float* sc = (float*)dynsm;
        const int bB = m0 >> 10;
        const int s0 = m0 & 1023;
#pragma unroll
        for (int pass = 0; pass < 2; ++pass) {
            __syncthreads();
            if (wc == pass) {
#pragma unroll
                for (int im = 0; im < 2; ++im)
#pragma unroll
                    for (int jn = 0; jn < 8; ++jn)
#pragma unroll
                        for (int p = 0; p < 2; ++p) {
                            int rloc = wr * 32 + im * 16 + r0l + p * 8;
                            int cloc = jn * 8 + c0l;
                            sc[rloc * 65 + cloc] = acc[im][jn][p * 2];
                            sc[rloc * 65 + cloc + 1] = acc[im][jn][p * 2 + 1];
                        }
            }
            __syncthreads();
            int nl = tid >> 2;
            int sblk = (tid & 3) * 32;
            int n = n0 + pass * 64 + nl;
            size_t obase = (((size_t)(bB * CC + n)) << 10) + s0 + sblk;
            float bn = bias[n];
#pragma unroll
            for (int j = 0; j < 32; j += 4) {
                float4 xr = *(const float4*)(resid + obase + j);
                float4 o;
                o.x = sc[(sblk + j + 0) * 65 + nl] + bn + xr.x;
                o.y = sc[(sblk + j + 1) * 65 + nl] + bn + xr.y;
                o.z = sc[(sblk + j + 2) * 65 + nl] + bn + xr.z;
                o.w = sc[(sblk + j + 3) * 65 + nl] + bn + xr.w;
                *(float4*)(C + obase + j) = o;
            }
        }
    }
}

// ---------------------------------------------------------------------------
// Fused attention: per CTA, 64 q-rows of one (b,h); loop 8 chunks of 128 keys.
// S = Q K^T -> exp -> P (smem) -> O += P V; normalize at end. No global P.
// ---------------------------------------------------------------------------
__global__ __launch_bounds__(256) void fused_attn() {
    extern __shared__ __align__(16) char dynsm[];
    const uint32_t sb = smem_u32(dynsm);
    const int tid = threadIdx.x;
    const int wid = tid >> 5;
    const int lane = tid & 31;
    const int wr2 = wid >> 2;   // 0..1: 32-row half
    const int wc4 = wid & 3;    // 0..3: j/d quarter
    const int lr = lane & 15, lhf = lane >> 4;
    const int r0l = lane >> 2;
    const int c0l = (lane & 3) * 2;

    const int m0 = blockIdx.x * 64;
    const int bh = blockIdx.y;
    const int b = bh >> 3, h2 = bh & 7;
    const fp16* Qg = g_q + ((size_t)bh * SS + m0) * DK;
    const fp16* Kg = g_k + (size_t)bh * SS * DK;
    const fp16* Vg = g_v + (size_t)bh * DK * SS;
    float* rowsum = (float*)(dynsm + OFF_RS);
    if (tid < 64) rowsum[tid] = 0.0f;

    // loaders
    auto issueK = [&](int c) {
        int r = tid >> 1, cb = (tid & 1) * 128;
        uint32_t d0 = sb + OFF_K + r * QSTR + cb * 2;
        const fp16* s0 = Kg + (size_t)(c * 128 + r) * DK + cb;
#pragma unroll
        for (int j = 0; j < 16; ++j) cpa16(d0 + j * 16, s0 + j * 8);
    };
    auto issueV = [&](int c) {
        uint32_t d0 = sb + OFF_V + tid * VSTR;
        const fp16* s0 = Vg + (size_t)tid * SS + c * 128;
#pragma unroll
        for (int j = 0; j < 16; ++j) cpa16(d0 + j * 16, s0 + j * 8);
    };

    // Q load (once)
    {
        int r = tid >> 2, cb = (tid & 3) * 64;
        uint32_t d0 = sb + OFF_Q + r * QSTR + cb * 2;
        const fp16* s0 = Qg + (size_t)r * DK + cb;
#pragma unroll
        for (int j = 0; j < 8; ++j) cpa16(d0 + j * 16, s0 + j * 8);
    }
    cpa_commit();
    issueK(0); cpa_commit();
    issueV(0); cpa_commit();

    // frag base offsets
    uint32_t aQ[2], bK[2], aP[2], bV[4];
#pragma unroll
    for (int im = 0; im < 2; ++im) {
        aQ[im] = OFF_Q + (wr2 * 32 + im * 16 + lr) * QSTR + lhf * 16;
        aP[im] = OFF_P + (wr2 * 32 + im * 16 + lr) * VSTR + lhf * 16;
    }
#pragma unroll
    for (int jn = 0; jn < 2; ++jn)
        bK[jn] = OFF_K + (wc4 * 32 + jn * 16 + lr) * QSTR + lhf * 16;
#pragma unroll
    for (int jn = 0; jn < 4; ++jn)
        bV[jn] = OFF_V + (wc4 * 64 + jn * 16 + lr) * VSTR + lhf * 16;

    float acco[2][8][4] = {};
    float rs[2][2] = {};
    fp16* Psm = (fp16*)(dynsm + OFF_P);

#pragma unroll 1
    for (int c = 0; c < 8; ++c) {
        // K(c) ready (Q too on c=0); one group (V(c)) may remain in flight
        if (c + 1 < 8) cpa_wait<1>(); else cpa_wait<1>();
        __syncthreads();

        // ---- S = Q @ K_chunk^T : M=64, N=128, K=256 ----
        float accs[2][4][4] = {};
#pragma unroll
        for (int ks = 0; ks < 16; ++ks) {
            const uint32_t kso = ks * 32;
            uint32_t a[2][4], bq[2][4];
            ldsm4(a[0], sb + aQ[0] + kso);
            ldsm4(a[1], sb + aQ[1] + kso);
            ldsm4(bq[0], sb + bK[0] + kso);
            ldsm4(bq[1], sb + bK[1] + kso);
#pragma unroll
            for (int im = 0; im < 2; ++im)
#pragma unroll
                for (int jn = 0; jn < 2; ++jn) {
                    mma16816(accs[im][jn * 2], a[im], bq[jn][0], bq[jn][2]);
                    mma16816(accs[im][jn * 2 + 1], a[im], bq[jn][1], bq[jn][3]);
                }
        }
        // exp -> P smem + row-sum accumulate
#pragma unroll
        for (int im = 0; im < 2; ++im)
#pragma unroll
            for (int jn = 0; jn < 4; ++jn)
#pragma unroll
                for (int p = 0; p < 2; ++p) {
                    int row = wr2 * 32 + im * 16 + r0l + p * 8;
                    int col = wc4 * 32 + jn * 8 + c0l;
                    float p0 = __expf(accs[im][jn][p * 2] * 0.0625f);
                    float p1 = __expf(accs[im][jn][p * 2 + 1] * 0.0625f);
                    rs[im][p] += p0 + p1;
                    __half2 h;
                    h.x = __float2half(p0);
                    h.y = __float2half(p1);
                    *(__half2*)(Psm + row * 136 + col) = h;
                }
        __syncthreads();                       // S reads + P writes complete
        if (c + 1 < 8) { issueK(c + 1); cpa_commit(); }
        if (c + 1 < 8) cpa_wait<1>(); else cpa_wait<0>();   // V(c) ready
        __syncthreads();

        // ---- O += P @ V_chunk : M=64, N=256, K=128 ----
#pragma unroll
        for (int ks = 0; ks < 8; ++ks) {
            const uint32_t kso = ks * 32;
            uint32_t a[2][4], bv[4][4];
            ldsm4(a[0], sb + aP[0] + kso);
            ldsm4(a[1], sb + aP[1] + kso);
#pragma unroll
            for (int jn = 0; jn < 4; ++jn) ldsm4(bv[jn], sb + bV[jn] + kso);
#pragma unroll
            for (int im = 0; im < 2; ++im)
#pragma unroll
                for (int jn = 0; jn < 4; ++jn) {
                    mma16816(acco[im][jn * 2], a[im], bv[jn][0], bv[jn][2]);
                    mma16816(acco[im][jn * 2 + 1], a[im], bv[jn][1], bv[jn][3]);
                }
        }
        __syncthreads();                       // P + V reads complete
        if (c + 1 < 8) { issueV(c + 1); cpa_commit(); }
    }

    // ---- row-sum reduction across lanes & warps ----
#pragma unroll
    for (int im = 0; im < 2; ++im)
#pragma unroll
        for (int p = 0; p < 2; ++p) {
            float s = rs[im][p];
            s += __shfl_xor_sync(0xffffffffu, s, 1);
            s += __shfl_xor_sync(0xffffffffu, s, 2);
            if ((lane & 3) == 0)
                atomicAdd(rowsum + wr2 * 32 + im * 16 + r0l + p * 8, s);
        }
    __syncthreads();

    // ---- normalize + store O ----
#pragma unroll
    for (int im = 0; im < 2; ++im)
#pragma unroll
        for (int p = 0; p < 2; ++p) {
            int ml = wr2 * 32 + im * 16 + r0l + p * 8;
            float inv = 1.0f / rowsum[ml];
            size_t base = ((size_t)(b * SS + m0 + ml)) * HD + h2 * DK + wc4 * 64;
#pragma unroll
            for (int jn = 0; jn < 8; ++jn) {
                __half2 h;
                h.x = __float2half(acco[im][jn][p * 2] * inv);
                h.y = __float2half(acco[im][jn][p * 2 + 1] * inv);
                *(__half2*)(g_ao + base + jn * 8 + c0l) = h;
            }
        }
}

// ---------------------------------------------------------------------------
extern "C" void kernel_launch(void* const* d_in, const int* in_sizes, int n_in,
                              void* d_out, int out_size) {
    const float* x  = (const float*)d_in[0];
    const float* Wp = (const float*)d_in[1];
    const float* bp = (const float*)d_in[2];
    const float* Wo = (const float*)d_in[3];
    const float* bo = (const float*)d_in[4];
    float* out = (float*)d_out;

    fp16 *xt, *WpT, *WoT, *ao;
    cudaGetSymbolAddress((void**)&xt, g_xt);
    cudaGetSymbolAddress((void**)&WpT, g_WpT);
    cudaGetSymbolAddress((void**)&WoT, g_WoT);
    cudaGetSymbolAddress((void**)&ao, g_ao);

    cudaFuncSetAttribute(gemm_fp16<0>, cudaFuncAttributeMaxDynamicSharedMemorySize, SMEM_DYN);
    cudaFuncSetAttribute(gemm_fp16<3>, cudaFuncAttributeMaxDynamicSharedMemorySize, SMEM_DYN);
    cudaFuncSetAttribute(fused_attn, cudaFuncAttributeMaxDynamicSharedMemorySize, SMEM_FA);

    dim3 tb(32, 8);
    convT<<<dim3(SS / 32, CC / 32, BB), tb>>>(x, xt, CC, SS);
    convT<<<dim3(QKVN / 32, CC / 32, 1), tb>>>(Wp, WpT, CC, QKVN);
    convT<<<dim3(CC / 32, HD / 32, 1), tb>>>(Wo, WoT, HD, CC);

    // QKV projection: [8192,256] @ [6144,256]^T  (V written transposed)
    gemm_fp16<0><<<dim3(QKVN / BN, (BB * SS) / BM, 1), 256, SMEM_DYN>>>(
        xt, WpT, nullptr, CC, CC, CC, bp, nullptr);

    // Fused attention: QK^T -> exp -> PV, normalized, straight to g_ao
    fused_attn<<<dim3(SS / 64, BB * NH), 256, SMEM_FA>>>();

    // Out projection + bias + residual
    gemm_fp16<3><<<dim3(CC / BN, (BB * SS) / BM, 1), 256, SMEM_DYN>>>(
        ao, WoT, out, HD, HD, HD, bo, x);
}

// round 15
// speedup vs baseline: 1.3043x; 1.3043x over previous
#include <cuda_runtime.h>
#include <cuda_fp16.h>
#include <cstdint>
#include <cstddef>

// ---------------------------------------------------------------------------
#define BB 8
#define CC 256
#define SS 1024
#define NH 8
#define DK 256
#define HD 2048
#define QKVN 6144

#define BM 128
#define BN 128
#define BKF 32                     // K elements per block
#define PAD 40                     // fp16 per smem row (80B; ldsm conflict-free)
#define TILEB (128 * PAD * 2)      // 10240 B per tile
#define STAGEB (2 * TILEB)         // A, B
#define NSTAGE 5
#define SMEM_DYN (NSTAGE * STAGEB) // 102400 B (2 CTAs/SM: 200 KB <= 228 KB)
#define SCP 132                    // fp16 pad for V-transpose staging

typedef __half fp16;

// ---------------------------------------------------------------------------
// Device scratch (allocation-free)
// ---------------------------------------------------------------------------
__device__ __align__(128) fp16 g_xt[BB * SS * CC];        // [b*S+s][c]
__device__ __align__(128) fp16 g_WpT[QKVN * CC];          // [n][k]
__device__ __align__(128) fp16 g_WoT[CC * HD];            // [n][k]
__device__ __align__(128) fp16 g_q[BB * NH * SS * DK];    // [bh][s][d] (pre-scaled 1/16)
__device__ __align__(128) fp16 g_k[BB * NH * SS * DK];    // [bh][s][d]
__device__ __align__(128) fp16 g_v[BB * NH * DK * SS];    // [bh][d][s]  TRANSPOSED
__device__ __align__(128) fp16 g_p[(size_t)BB * NH * SS * SS]; // unnormalized exp
__device__ __align__(128) float g_l[BB * NH * SS];        // row sums of exp
__device__ __align__(128) fp16 g_ao[BB * SS * HD];        // [b*S+s][h*DK+d]

// ---------------------------------------------------------------------------
// PTX helpers
// ---------------------------------------------------------------------------
__device__ __forceinline__ uint32_t smem_u32(const void* p) {
    uint32_t a;
    asm("{ .reg .u64 t; cvta.to.shared.u64 t, %1; cvt.u32.u64 %0, t; }"
        : "=r"(a) : "l"(p));
    return a;
}
__device__ __forceinline__ void cpa16(uint32_t dst, const void* src) {
    asm volatile("cp.async.cg.shared.global [%0], [%1], 16;"
                 :: "r"(dst), "l"(src) : "memory");
}
__device__ __forceinline__ void cpa_commit() {
    asm volatile("cp.async.commit_group;" ::: "memory");
}
template <int N> __device__ __forceinline__ void cpa_wait() {
    asm volatile("cp.async.wait_group %0;" :: "n"(N) : "memory");
}
__device__ __forceinline__ void ldsm4(uint32_t* r, uint32_t addr) {
    asm volatile("ldmatrix.sync.aligned.m8n8.x4.shared.b16 {%0,%1,%2,%3}, [%4];"
                 : "=r"(r[0]), "=r"(r[1]), "=r"(r[2]), "=r"(r[3]) : "r"(addr));
}
__device__ __forceinline__ void mma16816(float* d, const uint32_t* a,
                                         uint32_t b0, uint32_t b1) {
    asm volatile(
        "mma.sync.aligned.m16n8k16.row.col.f32.f16.f16.f32 "
        "{%0,%1,%2,%3}, {%4,%5,%6,%7}, {%8,%9}, {%0,%1,%2,%3};"
        : "+f"(d[0]), "+f"(d[1]), "+f"(d[2]), "+f"(d[3])
        : "r"(a[0]), "r"(a[1]), "r"(a[2]), "r"(a[3]), "r"(b0), "r"(b1));
}

// ---------------------------------------------------------------------------
// fp32 [Z][R][C] -> transposed fp16 [Z][C][R]
// ---------------------------------------------------------------------------
__global__ __launch_bounds__(256) void convT(const float* __restrict__ in,
                                             fp16* __restrict__ o, int R, int C) {
    __shared__ float t[32][33];
    int z = blockIdx.z;
    const float* I = in + (size_t)z * R * C;
    size_t ob = (size_t)z * R * C;
    int c0 = blockIdx.x * 32, r0 = blockIdx.y * 32;
    int x = threadIdx.x, y = threadIdx.y;
#pragma unroll
    for (int i = 0; i < 32; i += 8)
        t[y + i][x] = I[(size_t)(r0 + y + i) * C + c0 + x];
    __syncthreads();
#pragma unroll
    for (int i = 0; i < 32; i += 8)
        o[ob + (size_t)(c0 + y + i) * R + r0 + x] = __float2half(t[x][y + i]);
}

// ---------------------------------------------------------------------------
// fp16 GEMM, 5-stage cp.async, split A/B issue, 1 sync/iter.
// C tile = A[128,K] * B[128,K]^T
// MODE 0: QKV -> bias; Q scaled 1/16 + scattered; K scattered;
//         V written TRANSPOSED via smem staging
// MODE 1: QK^T -> P~ = exp(s) fp16 + atomic row sums into lsum
// MODE 2: PV -> normalize by 1/lsum[row], fp16 attnout
// MODE 3: proj -> bias + residual + transposed fp32 store
// ---------------------------------------------------------------------------
template <int MODE>
__global__ __launch_bounds__(256, 2) void gemm_fp16(
    const fp16* __restrict__ A, const fp16* __restrict__ B,
    float* __restrict__ C, fp16* __restrict__ Cf,
    int K, int ldA, int ldB, int ldC, size_t Az, size_t Bz, size_t Cz,
    const float* __restrict__ bias, const float* __restrict__ resid,
    float* __restrict__ lsum) {
    extern __shared__ __align__(16) char dynsm[];
    const uint32_t sbase = smem_u32(dynsm);

    const int tid = threadIdx.x;
    const int wid = tid >> 5;
    const int lane = tid & 31;
    const int wr = wid >> 1;
    const int wc = wid & 1;

    const int z = blockIdx.z;
    const int m0 = blockIdx.y * BM;
    const int n0 = blockIdx.x * BN;
    const fp16* tA = A + Az * z + (size_t)m0 * ldA;
    const fp16* tB = B + Bz * z + (size_t)n0 * ldB;
    const int NKB = K / BKF;

    const int crow = tid >> 1;
    const int ccol = (tid & 1) * 16;

    auto issueA = [&](int kb, int stg) {
        uint32_t sb = sbase + stg * STAGEB + (crow * PAD + ccol) * 2;
        const fp16* ga = tA + (size_t)crow * ldA + kb * BKF + ccol;
        cpa16(sb, ga);
        cpa16(sb + 16, ga + 8);
    };
    auto issueB = [&](int kb, int stg) {
        uint32_t sb = sbase + stg * STAGEB + TILEB + (crow * PAD + ccol) * 2;
        const fp16* gb = tB + (size_t)crow * ldB + kb * BKF + ccol;
        cpa16(sb, gb);
        cpa16(sb + 16, gb + 8);
    };

    const int lr = lane & 15, lhf = lane >> 4;
    uint32_t aoff[2], boff[4];
#pragma unroll
    for (int im = 0; im < 2; ++im)
        aoff[im] = ((wr * 32 + im * 16 + lr) * PAD + lhf * 8) * 2;
#pragma unroll
    for (int jn = 0; jn < 4; ++jn)
        boff[jn] = ((wc * 64 + jn * 16 + lr) * PAD + lhf * 8) * 2;

    float acc[2][8][4] = {};

    // prologue: prefetch 4 stages
#pragma unroll
    for (int s = 0; s < 4; ++s) {
        issueA(s, s); issueB(s, s); cpa_commit();
    }

    for (int kb = 0; kb < NKB; ++kb) {
        if (kb + 4 <= NKB) cpa_wait<3>();
        else if (kb + 3 == NKB) cpa_wait<2>();
        else if (kb + 2 == NKB) cpa_wait<1>();
        else cpa_wait<0>();
        __syncthreads();

        const bool pf = (kb + 4 < NKB);
        const int pstg = (kb + 4) % NSTAGE;
        if (pf) issueA(kb + 4, pstg);

        const int stg = kb % NSTAGE;
        const uint32_t sA = sbase + stg * STAGEB;
        const uint32_t sB = sA + TILEB;

        uint32_t af[2][2][4], bf[2][4][4];
#pragma unroll
        for (int ks = 0; ks < 2; ++ks) {
            const uint32_t kso = ks * 32;
            ldsm4(af[ks][0], sA + aoff[0] + kso);
            ldsm4(af[ks][1], sA + aoff[1] + kso);
#pragma unroll
            for (int jn = 0; jn < 4; ++jn) ldsm4(bf[ks][jn], sB + boff[jn] + kso);
        }

        if (pf) issueB(kb + 4, pstg);

#pragma unroll
        for (int ks = 0; ks < 2; ++ks)
#pragma unroll
            for (int im = 0; im < 2; ++im)
#pragma unroll
                for (int jn = 0; jn < 4; ++jn) {
                    mma16816(acc[im][jn * 2], af[ks][im], bf[ks][jn][0], bf[ks][jn][2]);
                    mma16816(acc[im][jn * 2 + 1], af[ks][im], bf[ks][jn][1], bf[ks][jn][3]);
                }
        if (pf) cpa_commit();
    }
    __syncthreads();

    // ---- epilogue ----
    const int r0l = lane >> 2;
    const int c0l = (lane & 3) * 2;

    if (MODE == 0) {
        const int hB = n0 / 768;
        const int loc0 = n0 % 768;
        const int seg = loc0 >> 8;
        const int d0 = loc0 & 255;
        if (seg < 2) {
            fp16* dst = (seg == 0) ? g_q : g_k;
            const float qs = (seg == 0) ? 0.0625f : 1.0f;   // fold softmax scale into Q
#pragma unroll
            for (int im = 0; im < 2; ++im)
#pragma unroll
                for (int jn = 0; jn < 8; ++jn)
#pragma unroll
                    for (int p = 0; p < 2; ++p) {
                        int m = m0 + wr * 32 + im * 16 + r0l + p * 8;
                        int nb = wc * 64 + jn * 8 + c0l;
                        int b = m >> 10, s2 = m & 1023;
                        size_t row = ((size_t)(b * NH + hB) * SS + s2) * DK + d0 + nb;
                        __half2 h;
                        h.x = __float2half((acc[im][jn][p * 2] + bias[n0 + nb]) * qs);
                        h.y = __float2half((acc[im][jn][p * 2 + 1] + bias[n0 + nb + 1]) * qs);
                        *(__half2*)(dst + row) = h;
                    }
        } else {
            // V: stage [m][d] in smem, write transposed [d][s] coalesced
            fp16* sc = (fp16*)dynsm;  // 128 x SCP fp16 = 33.8 KB
#pragma unroll
            for (int im = 0; im < 2; ++im)
#pragma unroll
                for (int jn = 0; jn < 8; ++jn)
#pragma unroll
                    for (int p = 0; p < 2; ++p) {
                        int ml = wr * 32 + im * 16 + r0l + p * 8;
                        int nb = wc * 64 + jn * 8 + c0l;
                        sc[ml * SCP + nb] =
                            __float2half(acc[im][jn][p * 2] + bias[n0 + nb]);
                        sc[ml * SCP + nb + 1] =
                            __float2half(acc[im][jn][p * 2 + 1] + bias[n0 + nb + 1]);
                    }
            __syncthreads();
            const int b = m0 >> 10;
            const int s0 = m0 & 1023;
            const int d = tid & 127;          // local d 0..127
            const int mh = (tid >> 7) * 64;   // m half: 0 or 64
            fp16* vrow = g_v + ((size_t)(b * NH + hB) * DK + d0 + d) * SS + s0 + mh;
#pragma unroll
            for (int j = 0; j < 64; j += 2) {
                __half2 h;
                h.x = sc[(mh + j) * SCP + d];
                h.y = sc[(mh + j + 1) * SCP + d];
                *(__half2*)(vrow + j) = h;
            }
        }
    } else if (MODE == 1) {
        fp16* Cb = Cf + Cz * z;
        float rsum[2][2] = {};
#pragma unroll
        for (int im = 0; im < 2; ++im)
#pragma unroll
            for (int p = 0; p < 2; ++p) {
                int m = m0 + wr * 32 + im * 16 + r0l + p * 8;
                float rs = 0.0f;
#pragma unroll
                for (int jn = 0; jn < 8; ++jn) {
                    int nb = wc * 64 + jn * 8 + c0l;
                    float p0 = __expf(acc[im][jn][p * 2]);
                    float p1 = __expf(acc[im][jn][p * 2 + 1]);
                    rs += p0 + p1;
                    __half2 h;
                    h.x = __float2half(p0);
                    h.y = __float2half(p1);
                    *(__half2*)(Cb + (size_t)m * ldC + n0 + nb) = h;
                }
                rsum[im][p] = rs;
            }
#pragma unroll
        for (int im = 0; im < 2; ++im)
#pragma unroll
            for (int p = 0; p < 2; ++p) {
                float s = rsum[im][p];
                s += __shfl_xor_sync(0xffffffffu, s, 1);
                s += __shfl_xor_sync(0xffffffffu, s, 2);
                if ((lane & 3) == 0) {
                    int m = m0 + wr * 32 + im * 16 + r0l + p * 8;
                    atomicAdd(lsum + (size_t)z * SS + m, s);
                }
            }
    } else if (MODE == 2) {
        int b = z >> 3, h2 = z & 7;
        size_t base = (size_t)b * SS * HD + h2 * DK;
        const float* lz = lsum + (size_t)z * SS;
#pragma unroll
        for (int im = 0; im < 2; ++im)
#pragma unroll
            for (int p = 0; p < 2; ++p) {
                int m = m0 + wr * 32 + im * 16 + r0l + p * 8;
                float inv = 1.0f / lz[m];
#pragma unroll
                for (int jn = 0; jn < 8; ++jn) {
                    int nb = wc * 64 + jn * 8 + c0l;
                    size_t idx = base + (size_t)m * HD + n0 + nb;
                    __half2 h;
                    h.x = __float2half(acc[im][jn][p * 2] * inv);
                    h.y = __float2half(acc[im][jn][p * 2 + 1] * inv);
                    *(__half2*)(g_ao + idx) = h;
                }
            }
    } else {  // MODE 3: smem transpose -> coalesced [B,C,S] store + bias + resid
        float* sc = (float*)dynsm;  // 128 x 65 fp32 = 33.3 KB (fits 100 KB)
        const int bB = m0 >> 10;
        const int s0 = m0 & 1023;
#pragma unroll
        for (int pass = 0; pass < 2; ++pass) {
            __syncthreads();
            if (wc == pass) {
#pragma unroll
                for (int im = 0; im < 2; ++im)
#pragma unroll
                    for (int jn = 0; jn < 8; ++jn)
#pragma unroll
                        for (int p = 0; p < 2; ++p) {
                            int rloc = wr * 32 + im * 16 + r0l + p * 8;
                            int cloc = jn * 8 + c0l;
                            sc[rloc * 65 + cloc] = acc[im][jn][p * 2];
                            sc[rloc * 65 + cloc + 1] = acc[im][jn][p * 2 + 1];
                        }
            }
            __syncthreads();
            int nl = tid >> 2;
            int sblk = (tid & 3) * 32;
            int n = n0 + pass * 64 + nl;
            size_t obase = (((size_t)(bB * CC + n)) << 10) + s0 + sblk;
            float bn = bias[n];
#pragma unroll
            for (int j = 0; j < 32; j += 4) {
                float4 xr = *(const float4*)(resid + obase + j);
                float4 o;
                o.x = sc[(sblk + j + 0) * 65 + nl] + bn + xr.x;
                o.y = sc[(sblk + j + 1) * 65 + nl] + bn + xr.y;
                o.z = sc[(sblk + j + 2) * 65 + nl] + bn + xr.z;
                o.w = sc[(sblk + j + 3) * 65 + nl] + bn + xr.w;
                *(float4*)(C + obase + j) = o;
            }
        }
    }
}

// ---------------------------------------------------------------------------
extern "C" void kernel_launch(void* const* d_in, const int* in_sizes, int n_in,
                              void* d_out, int out_size) {
    const float* x  = (const float*)d_in[0];
    const float* Wp = (const float*)d_in[1];
    const float* bp = (const float*)d_in[2];
    const float* Wo = (const float*)d_in[3];
    const float* bo = (const float*)d_in[4];
    float* out = (float*)d_out;

    fp16 *xt, *WpT, *WoT, *q, *k, *v, *pp, *ao;
    float* lp;
    cudaGetSymbolAddress((void**)&xt, g_xt);
    cudaGetSymbolAddress((void**)&WpT, g_WpT);
    cudaGetSymbolAddress((void**)&WoT, g_WoT);
    cudaGetSymbolAddress((void**)&q, g_q);
    cudaGetSymbolAddress((void**)&k, g_k);
    cudaGetSymbolAddress((void**)&v, g_v);
    cudaGetSymbolAddress((void**)&pp, g_p);
    cudaGetSymbolAddress((void**)&ao, g_ao);
    cudaGetSymbolAddress((void**)&lp, g_l);

    cudaFuncSetAttribute(gemm_fp16<0>, cudaFuncAttributeMaxDynamicSharedMemorySize, SMEM_DYN);
    cudaFuncSetAttribute(gemm_fp16<1>, cudaFuncAttributeMaxDynamicSharedMemorySize, SMEM_DYN);
    cudaFuncSetAttribute(gemm_fp16<2>, cudaFuncAttributeMaxDynamicSharedMemorySize, SMEM_DYN);
    cudaFuncSetAttribute(gemm_fp16<3>, cudaFuncAttributeMaxDynamicSharedMemorySize, SMEM_DYN);

    cudaMemsetAsync(lp, 0, BB * NH * SS * sizeof(float), 0);

    dim3 tb(32, 8);
    convT<<<dim3(SS / 32, CC / 32, BB), tb>>>(x, xt, CC, SS);
    convT<<<dim3(QKVN / 32, CC / 32, 1), tb>>>(Wp, WpT, CC, QKVN);
    convT<<<dim3(CC / 32, HD / 32, 1), tb>>>(Wo, WoT, HD, CC);

    // QKV projection: [8192,256] @ [6144,256]^T  (Q pre-scaled, V transposed)
    gemm_fp16<0><<<dim3(QKVN / BN, (BB * SS) / BM, 1), 256, SMEM_DYN>>>(
        xt, WpT, nullptr, nullptr, CC, CC, CC, 0, 0, 0, 0, bp, nullptr, nullptr);

    // Q K^T -> P~ = exp(s) fp16 + row sums  (scale already folded into Q)
    gemm_fp16<1><<<dim3(SS / BN, SS / BM, BB * NH), 256, SMEM_DYN>>>(
        q, k, nullptr, pp, DK, DK, DK, SS,
        (size_t)SS * DK, (size_t)SS * DK, (size_t)SS * SS, nullptr, nullptr, lp);

    // P~ V -> normalized attnout (B = V^T, [bh][d][s])
    gemm_fp16<2><<<dim3(DK / BN, SS / BM, BB * NH), 256, SMEM_DYN>>>(
        pp, v, nullptr, nullptr, SS, SS, SS, 0,
        (size_t)SS * SS, (size_t)DK * SS, 0, nullptr, nullptr, lp);

    // Out projection + bias + residual
    gemm_fp16<3><<<dim3(CC / BN, (BB * SS) / BM, 1), 256, SMEM_DYN>>>(
        ao, WoT, out, nullptr, HD, HD, HD, 0, 0, 0, 0, bo, x, nullptr);
}